// round 3
// baseline (speedup 1.0000x reference)
#include <cuda_runtime.h>

#define N_NODES 100000
#define N_EDGES_MAX 1600000
#define D 128
#define ND (N_NODES * D)
#define TROWS 64
#define NT ((N_NODES + TROWS - 1) / TROWS)   // 1563
// smem: W[128*128] + 2 x Z[64*128] + rs[2048] floats
#define FUSED_SMEM_FLOATS (128*128 + 2*TROWS*128 + 2048)
#define FUSED_SMEM_BYTES (FUSED_SMEM_FLOATS * 4)

__device__ float g_y[ND];
__device__ float g_stats[2 * D];   // zero-init; re-zeroed by finalize each use
__device__ float g_scale[D];
__device__ float g_shift[D];
__device__ int g_deg[N_NODES];
__device__ int g_off[N_NODES + 1];
__device__ int g_cur[N_NODES];
__device__ int g_eidx[N_EDGES_MAX];

// ---------------- small helpers ----------------
__device__ __forceinline__ unsigned long long pk2(float a, float b) {
    unsigned long long r;
    asm("mov.b64 %0, {%1, %2};" : "=l"(r) : "f"(a), "f"(b));
    return r;
}
__device__ __forceinline__ void unpk2(float& a, float& b, unsigned long long v) {
    asm("mov.b64 {%0, %1}, %2;" : "=f"(a), "=f"(b) : "l"(v));
}
__device__ __forceinline__ void ffma2(unsigned long long& d, unsigned long long a,
                                      unsigned long long b) {
    asm("fma.rn.f32x2 %0, %1, %2, %0;" : "+l"(d) : "l"(a), "l"(b));
}
#define BAR_SYNC512(id)   asm volatile("bar.sync %0, 512;"   :: "r"(id) : "memory")
#define BAR_ARRIVE512(id) asm volatile("bar.arrive %0, 512;" :: "r"(id) : "memory")
#define BAR_SYNC_CONS()   asm volatile("bar.sync 5, 256;" ::: "memory")

// ---------------- CSR build (once per launch) ----------------
__global__ void zero_deg_k() {
    for (int i = blockIdx.x * blockDim.x + threadIdx.x; i < N_NODES; i += gridDim.x * blockDim.x)
        g_deg[i] = 0;
}

__global__ void hist_k(const int* __restrict__ dst, int nE) {
    for (int e = blockIdx.x * blockDim.x + threadIdx.x; e < nE; e += gridDim.x * blockDim.x)
        atomicAdd(&g_deg[dst[e]], 1);
}

__global__ void scan_k(int nE) {
    __shared__ int sm[1024];
    const int t = threadIdx.x;
    const int CH = (N_NODES + 1023) / 1024;  // 98
    int base = t * CH;
    int s = 0;
    for (int i = 0; i < CH; i++) {
        int idx = base + i;
        if (idx < N_NODES) s += g_deg[idx];
    }
    sm[t] = s;
    __syncthreads();
    for (int d = 1; d < 1024; d <<= 1) {
        int v = (t >= d) ? sm[t - d] : 0;
        __syncthreads();
        sm[t] += v;
        __syncthreads();
    }
    int off = sm[t] - s;  // exclusive
    for (int i = 0; i < CH; i++) {
        int idx = base + i;
        if (idx < N_NODES) {
            g_off[idx] = off;
            g_cur[idx] = off;
            off += g_deg[idx];
        }
    }
    if (t == 1023) g_off[N_NODES] = nE;
}

__global__ void fill_k(const int* __restrict__ src, const int* __restrict__ dst, int nE) {
    for (int e = blockIdx.x * blockDim.x + threadIdx.x; e < nE; e += gridDim.x * blockDim.x) {
        int p = atomicAdd(&g_cur[dst[e]], 1);
        g_eidx[p] = src[e];
    }
}

// ---------------- warp-specialized fused layer ----------------
// Producers (warps 0-7): CSR gather -> double-buffered Z tile in smem
// Consumers (warps 8-15): y = Z @ W + b (FFMA2), store g_y, BN1 stats
__global__ void __launch_bounds__(512, 1)
fused_layer_k(const float* __restrict__ h, const float* __restrict__ W,
              const float* __restrict__ b, const float* __restrict__ eps, int layer) {
    extern __shared__ float sm[];
    float* Ws  = sm;                       // 16384
    float* zb0 = sm + 128 * 128;           // 8192
    float* zb1 = zb0 + TROWS * 128;        // 8192
    float* rs  = zb1 + TROWS * 128;        // 2048

    const int tid = threadIdx.x;
    const int warp = tid >> 5, lane = tid & 31;
    const bool producer = warp < 8;
    const float e1 = 1.0f + __ldg(&eps[layer]);

    const int cw = warp - 8;      // consumer warp id 0..7
    const int c0 = lane * 4;

    unsigned long long bxy = 0, bzw = 0;
    if (!producer) {
        // consumers load W, then consumer-group barrier
        float4* Ws4 = (float4*)Ws;
        const float4* W4 = (const float4*)W;
        #pragma unroll 4
        for (int i = tid - 256; i < 128 * 128 / 4; i += 256) Ws4[i] = W4[i];
        float4 bb = ((const float4*)b)[lane];
        bxy = pk2(bb.x, bb.y);
        bzw = pk2(bb.z, bb.w);
        BAR_SYNC_CONS();
    }

    float sx = 0.f, sy = 0.f, szv = 0.f, swv = 0.f;
    float qx = 0.f, qy = 0.f, qz = 0.f, qw = 0.f;

    int it = 0;
    for (int tile = blockIdx.x; tile < NT; tile += gridDim.x, ++it) {
        const int buf = it & 1;
        float* zs = buf ? zb1 : zb0;

        if (producer) {
            if (it >= 2) BAR_SYNC512(3 + buf);   // wait buffer empty
            const float4* hp = (const float4*)h;
            float4* zs4 = (float4*)zs;
            #pragma unroll
            for (int r = 0; r < 8; r++) {
                int wr = warp * 8 + r;
                int row = tile * TROWS + wr;
                float4 acc = make_float4(0.f, 0.f, 0.f, 0.f);
                if (row < N_NODES) {
                    float4 v = hp[(size_t)row * 32 + lane];
                    acc.x = e1 * v.x; acc.y = e1 * v.y; acc.z = e1 * v.z; acc.w = e1 * v.w;
                    int start = g_off[row];
                    int deg = g_off[row + 1] - start;
                    for (int basee = 0; basee < deg; basee += 32) {
                        int m = deg - basee; if (m > 32) m = 32;
                        int idx = 0;
                        if (lane < m) idx = g_eidx[start + basee + lane];
                        int l = 0;
                        for (; l + 4 <= m; l += 4) {
                            int s0 = __shfl_sync(0xffffffffu, idx, l);
                            int s1 = __shfl_sync(0xffffffffu, idx, l + 1);
                            int s2 = __shfl_sync(0xffffffffu, idx, l + 2);
                            int s3 = __shfl_sync(0xffffffffu, idx, l + 3);
                            float4 a0 = hp[(size_t)s0 * 32 + lane];
                            float4 a1 = hp[(size_t)s1 * 32 + lane];
                            float4 a2 = hp[(size_t)s2 * 32 + lane];
                            float4 a3 = hp[(size_t)s3 * 32 + lane];
                            acc.x += (a0.x + a1.x) + (a2.x + a3.x);
                            acc.y += (a0.y + a1.y) + (a2.y + a3.y);
                            acc.z += (a0.z + a1.z) + (a2.z + a3.z);
                            acc.w += (a0.w + a1.w) + (a2.w + a3.w);
                        }
                        for (; l < m; l++) {
                            int s0 = __shfl_sync(0xffffffffu, idx, l);
                            float4 a0 = hp[(size_t)s0 * 32 + lane];
                            acc.x += a0.x; acc.y += a0.y; acc.z += a0.z; acc.w += a0.w;
                        }
                    }
                }
                zs4[wr * 32 + lane] = acc;
            }
            BAR_ARRIVE512(1 + buf);              // mark buffer full
        } else {
            BAR_SYNC512(1 + buf);                // wait buffer full
            unsigned long long axy[8], azw[8];
            #pragma unroll
            for (int r = 0; r < 8; r++) { axy[r] = bxy; azw[r] = bzw; }

            #pragma unroll 4
            for (int k = 0; k < 128; k++) {
                float4 w = *(float4*)&Ws[k * 128 + c0];
                unsigned long long wxy = pk2(w.x, w.y);
                unsigned long long wzw = pk2(w.z, w.w);
                #pragma unroll
                for (int r = 0; r < 8; r++) {
                    float z = zs[(cw * 8 + r) * 128 + k];
                    unsigned long long zz = pk2(z, z);
                    ffma2(axy[r], zz, wxy);
                    ffma2(azw[r], zz, wzw);
                }
            }

            float4* y4 = (float4*)g_y;
            #pragma unroll
            for (int r = 0; r < 8; r++) {
                int row = tile * TROWS + cw * 8 + r;
                if (row < N_NODES) {
                    float4 v;
                    unpk2(v.x, v.y, axy[r]);
                    unpk2(v.z, v.w, azw[r]);
                    y4[(size_t)row * 32 + lane] = v;
                    sx += v.x; sy += v.y; szv += v.z; swv += v.w;
                    qx += v.x * v.x; qy += v.y * v.y; qz += v.z * v.z; qw += v.w * v.w;
                }
            }
            BAR_ARRIVE512(3 + buf);              // mark buffer empty
        }
    }

    if (!producer) {
        // reduce BN1 stats across consumer warps
        rs[cw * 128 + c0 + 0] = sx;  rs[cw * 128 + c0 + 1] = sy;
        rs[cw * 128 + c0 + 2] = szv; rs[cw * 128 + c0 + 3] = swv;
        rs[1024 + cw * 128 + c0 + 0] = qx; rs[1024 + cw * 128 + c0 + 1] = qy;
        rs[1024 + cw * 128 + c0 + 2] = qz; rs[1024 + cw * 128 + c0 + 3] = qw;
        BAR_SYNC_CONS();
        int t = tid - 256;
        int col = t & 127;
        int so = (t >> 7) * 1024;
        float v = 0.f;
        #pragma unroll
        for (int w = 0; w < 8; w++) v += rs[so + w * 128 + col];
        atomicAdd(&g_stats[(t >> 7) * 128 + col], v);
    }
}

// consume g_stats -> scale/shift, re-zero g_stats (replay-invariant)
__global__ void finalize_k(const float* __restrict__ gamma, const float* __restrict__ beta) {
    int c = threadIdx.x;
    float sum = g_stats[c];
    float sq = g_stats[128 + c];
    float mean = sum * (1.0f / N_NODES);
    float var = sq * (1.0f / N_NODES) - mean * mean;
    float scl = rsqrtf(var + 1e-5f) * gamma[c];
    g_scale[c] = scl;
    g_shift[c] = beta[c] - mean * scl;
    g_stats[c] = 0.f;
    g_stats[128 + c] = 0.f;
}

// y = relu(y*scale+shift) in place, accumulate BN2 stats
__global__ void bn_relu_stats_k() {
    __shared__ float rs[2048];
    int tid = threadIdx.x, lane = tid & 31, warp = tid >> 5;
    float4 sc = ((const float4*)g_scale)[lane];
    float4 sh = ((const float4*)g_shift)[lane];
    float4 s = make_float4(0.f, 0.f, 0.f, 0.f);
    float4 q = make_float4(0.f, 0.f, 0.f, 0.f);
    float4* y4 = (float4*)g_y;
    int n4 = ND / 4;
    for (int i = blockIdx.x * 256 + tid; i < n4; i += gridDim.x * 256) {
        float4 v = y4[i];
        v.x = fmaxf(fmaf(v.x, sc.x, sh.x), 0.f);
        v.y = fmaxf(fmaf(v.y, sc.y, sh.y), 0.f);
        v.z = fmaxf(fmaf(v.z, sc.z, sh.z), 0.f);
        v.w = fmaxf(fmaf(v.w, sc.w, sh.w), 0.f);
        y4[i] = v;
        s.x += v.x; s.y += v.y; s.z += v.z; s.w += v.w;
        q.x += v.x * v.x; q.y += v.y * v.y; q.z += v.z * v.z; q.w += v.w * v.w;
    }
    int c0 = lane * 4;
    rs[warp * 128 + c0 + 0] = s.x; rs[warp * 128 + c0 + 1] = s.y;
    rs[warp * 128 + c0 + 2] = s.z; rs[warp * 128 + c0 + 3] = s.w;
    rs[1024 + warp * 128 + c0 + 0] = q.x; rs[1024 + warp * 128 + c0 + 1] = q.y;
    rs[1024 + warp * 128 + c0 + 2] = q.z; rs[1024 + warp * 128 + c0 + 3] = q.w;
    __syncthreads();
    int col = tid & 127;
    int so = (tid >> 7) * 1024;
    float v = 0.f;
    #pragma unroll
    for (int w = 0; w < 8; w++) v += rs[so + w * 128 + col];
    atomicAdd(&g_stats[(tid >> 7) * 128 + col], v);
}

// out = relu(y*scale+shift)  -> next layer's h
__global__ void bn_relu_out_k(float* __restrict__ out) {
    int tid = threadIdx.x, lane = tid & 31;
    float4 sc = ((const float4*)g_scale)[lane];
    float4 sh = ((const float4*)g_shift)[lane];
    const float4* y4 = (const float4*)g_y;
    float4* o4 = (float4*)out;
    int n4 = ND / 4;
    for (int i = blockIdx.x * 256 + tid; i < n4; i += gridDim.x * 256) {
        float4 v = y4[i];
        v.x = fmaxf(fmaf(v.x, sc.x, sh.x), 0.f);
        v.y = fmaxf(fmaf(v.y, sc.y, sh.y), 0.f);
        v.z = fmaxf(fmaf(v.z, sc.z, sh.z), 0.f);
        v.w = fmaxf(fmaf(v.w, sc.w, sh.w), 0.f);
        o4[i] = v;
    }
}

extern "C" void kernel_launch(void* const* d_in, const int* in_sizes, int n_in,
                              void* d_out, int out_size) {
    const float* features = (const float*)d_in[0];
    const float* W   = (const float*)d_in[1];
    const float* b   = (const float*)d_in[2];
    const float* eps = (const float*)d_in[3];
    const float* g1  = (const float*)d_in[4];
    const float* be1 = (const float*)d_in[5];
    const float* g2  = (const float*)d_in[6];
    const float* be2 = (const float*)d_in[7];
    const int* src   = (const int*)d_in[8];
    const int* dst   = (const int*)d_in[9];
    int nE = in_sizes[8];
    float* out = (float*)d_out;

    static bool once = []() {
        cudaFuncSetAttribute(fused_layer_k, cudaFuncAttributeMaxDynamicSharedMemorySize,
                             FUSED_SMEM_BYTES);
        return true;
    }();
    (void)once;

    // slab 0 = input features
    cudaMemcpyAsync(out, features, (size_t)ND * sizeof(float), cudaMemcpyDeviceToDevice);

    // build CSR (dst -> list of src) once
    zero_deg_k<<<392, 256>>>();
    hist_k<<<6250, 256>>>(dst, nE);
    scan_k<<<1, 1024>>>(nE);
    fill_k<<<6250, 256>>>(src, dst, nE);

    for (int i = 0; i < 3; i++) {
        const float* h = out + (size_t)i * ND;
        float* hn = out + (size_t)(i + 1) * ND;
        fused_layer_k<<<148, 512, FUSED_SMEM_BYTES>>>(
            h, W + (size_t)i * D * D, b + (size_t)i * D, eps, i);
        finalize_k<<<1, 128>>>(g1 + i * D, be1 + i * D);
        bn_relu_stats_k<<<1184, 256>>>();
        finalize_k<<<1, 128>>>(g2 + i * D, be2 + i * D);
        bn_relu_out_k<<<1184, 256>>>(hn);
    }
}

// round 5
// speedup vs baseline: 1.1101x; 1.1101x over previous
#include <cuda_runtime.h>

#define N_NODES 100000
#define N_EDGES_MAX 1600000
#define D 128
#define ND (N_NODES * D)
#define GROWS 64
// smem: Wp[128*128] + z[64*128] + red[2048] floats
#define GEMM_SMEM_FLOATS (128*128 + GROWS*128 + 2048)
#define GEMM_SMEM_BYTES (GEMM_SMEM_FLOATS * 4)

typedef unsigned long long ull;

__device__ float g_y[ND];
__device__ float g_stats[2 * D];     // zero-init; re-zeroed by finalize each use
__device__ float g_scale[2][D];
__device__ float g_shift[2][D];
__device__ int g_deg[N_NODES];
__device__ int g_off[N_NODES + 1];
__device__ int g_cur[N_NODES];
__device__ int g_eidx[N_EDGES_MAX];

__device__ __forceinline__ void ffma2(ull& d, ull a, ull b) {
    asm("fma.rn.f32x2 %0, %1, %2, %0;" : "+l"(d) : "l"(a), "l"(b));
}
__device__ __forceinline__ void unpk2(float& a, float& b, ull v) {
    asm("mov.b64 {%0, %1}, %2;" : "=f"(a), "=f"(b) : "l"(v));
}

// ---------------- CSR build (once per launch) ----------------
__global__ void zero_deg_k() {
    for (int i = blockIdx.x * blockDim.x + threadIdx.x; i < N_NODES; i += gridDim.x * blockDim.x)
        g_deg[i] = 0;
}

__global__ void hist_k(const int* __restrict__ dst, int nE) {
    for (int e = blockIdx.x * blockDim.x + threadIdx.x; e < nE; e += gridDim.x * blockDim.x)
        atomicAdd(&g_deg[dst[e]], 1);
}

__global__ void scan_k(int nE) {
    __shared__ int sm[1024];
    const int t = threadIdx.x;
    const int CH = (N_NODES + 1023) / 1024;  // 98
    int base = t * CH;
    int s = 0;
    for (int i = 0; i < CH; i++) {
        int idx = base + i;
        if (idx < N_NODES) s += g_deg[idx];
    }
    sm[t] = s;
    __syncthreads();
    for (int d = 1; d < 1024; d <<= 1) {
        int v = (t >= d) ? sm[t - d] : 0;
        __syncthreads();
        sm[t] += v;
        __syncthreads();
    }
    int off = sm[t] - s;  // exclusive
    for (int i = 0; i < CH; i++) {
        int idx = base + i;
        if (idx < N_NODES) {
            g_off[idx] = off;
            g_cur[idx] = off;
            off += g_deg[idx];
        }
    }
    if (t == 1023) g_off[N_NODES] = nE;
}

__global__ void fill_k(const int* __restrict__ src, const int* __restrict__ dst, int nE) {
    for (int e = blockIdx.x * blockDim.x + threadIdx.x; e < nE; e += gridDim.x * blockDim.x) {
        int p = atomicAdd(&g_cur[dst[e]], 1);
        g_eidx[p] = src[e];
    }
}

// ---------------- fused gather + GEMM(FFMA2) + BN1 stats ----------------
__global__ void __launch_bounds__(256, 2)
gather_gemm_stats_k(const float* __restrict__ h, const float* __restrict__ W,
                    const float* __restrict__ b, const float* __restrict__ eps,
                    int layer) {
    extern __shared__ float sm[];
    float* Wp = sm;                            // 16384 (k-pair interleaved)
    float* zs = sm + 128 * 128;                // 8192
    float* rs = sm + 128 * 128 + GROWS * 128;  // 2048

    const int tid = threadIdx.x;
    const int warp = tid >> 5, lane = tid & 31;
    const int row0 = blockIdx.x * GROWS;
    const float e1 = 1.0f + __ldg(&eps[layer]);

    // load W, storing k-pair interleaved: Wp[(k/2)*256 + 2*c + (k&1)] = W[k][c]
    {
        const float4* W4 = (const float4*)W;
        #pragma unroll 4
        for (int i = tid; i < 128 * 128 / 4; i += 256) {
            int k = i >> 5;
            int c = (i & 31) * 4;
            float4 v = W4[i];
            float* base = &Wp[(k >> 1) * 256 + (k & 1)];
            base[2 * c + 0] = v.x;
            base[2 * c + 2] = v.y;
            base[2 * c + 4] = v.z;
            base[2 * c + 6] = v.w;
        }
    }

    // gather phase: each warp builds 8 rows of Z in smem (8-wide neighbor ILP)
    {
        const float4* hp = (const float4*)h;
        float4* zs4 = (float4*)zs;
        #pragma unroll
        for (int r = 0; r < 8; r++) {
            int wr = warp * 8 + r;
            int row = row0 + wr;
            float4 acc = make_float4(0.f, 0.f, 0.f, 0.f);
            if (row < N_NODES) {
                float4 v = hp[(size_t)row * 32 + lane];
                acc.x = e1 * v.x; acc.y = e1 * v.y; acc.z = e1 * v.z; acc.w = e1 * v.w;
                int start = g_off[row];
                int deg = g_off[row + 1] - start;
                for (int basee = 0; basee < deg; basee += 32) {
                    int m = deg - basee; if (m > 32) m = 32;
                    int idx = 0;
                    if (lane < m) idx = g_eidx[start + basee + lane];
                    int l = 0;
                    for (; l + 8 <= m; l += 8) {
                        int s0 = __shfl_sync(0xffffffffu, idx, l);
                        int s1 = __shfl_sync(0xffffffffu, idx, l + 1);
                        int s2 = __shfl_sync(0xffffffffu, idx, l + 2);
                        int s3 = __shfl_sync(0xffffffffu, idx, l + 3);
                        int s4 = __shfl_sync(0xffffffffu, idx, l + 4);
                        int s5 = __shfl_sync(0xffffffffu, idx, l + 5);
                        int s6 = __shfl_sync(0xffffffffu, idx, l + 6);
                        int s7 = __shfl_sync(0xffffffffu, idx, l + 7);
                        float4 a0 = hp[(size_t)s0 * 32 + lane];
                        float4 a1 = hp[(size_t)s1 * 32 + lane];
                        float4 a2 = hp[(size_t)s2 * 32 + lane];
                        float4 a3 = hp[(size_t)s3 * 32 + lane];
                        float4 a4 = hp[(size_t)s4 * 32 + lane];
                        float4 a5 = hp[(size_t)s5 * 32 + lane];
                        float4 a6 = hp[(size_t)s6 * 32 + lane];
                        float4 a7 = hp[(size_t)s7 * 32 + lane];
                        acc.x += ((a0.x + a1.x) + (a2.x + a3.x)) + ((a4.x + a5.x) + (a6.x + a7.x));
                        acc.y += ((a0.y + a1.y) + (a2.y + a3.y)) + ((a4.y + a5.y) + (a6.y + a7.y));
                        acc.z += ((a0.z + a1.z) + (a2.z + a3.z)) + ((a4.z + a5.z) + (a6.z + a7.z));
                        acc.w += ((a0.w + a1.w) + (a2.w + a3.w)) + ((a4.w + a5.w) + (a6.w + a7.w));
                    }
                    for (; l < m; l++) {
                        int s0 = __shfl_sync(0xffffffffu, idx, l);
                        float4 a0 = hp[(size_t)s0 * 32 + lane];
                        acc.x += a0.x; acc.y += a0.y; acc.z += a0.z; acc.w += a0.w;
                    }
                }
            }
            zs4[wr * 32 + lane] = acc;
        }
    }
    __syncthreads();

    // GEMM phase: k-paired FFMA2, accumulators hold (even-k partial, odd-k partial)
    const int c0 = lane * 4;
    ull acc[8][4];
    #pragma unroll
    for (int r = 0; r < 8; r++)
        #pragma unroll
        for (int j = 0; j < 4; j++) acc[r][j] = 0ull;

    #pragma unroll 2
    for (int k = 0; k < 128; k += 4) {
        int k2 = k >> 1;
        ulonglong2 wa0 = *(ulonglong2*)&Wp[(k2 + 0) * 256 + 2 * c0];      // cols c0,c0+1 @ (k,k+1)
        ulonglong2 wa1 = *(ulonglong2*)&Wp[(k2 + 0) * 256 + 2 * c0 + 4];  // cols c0+2,c0+3
        ulonglong2 wb0 = *(ulonglong2*)&Wp[(k2 + 1) * 256 + 2 * c0];      // @ (k+2,k+3)
        ulonglong2 wb1 = *(ulonglong2*)&Wp[(k2 + 1) * 256 + 2 * c0 + 4];
        #pragma unroll
        for (int r = 0; r < 8; r++) {
            ulonglong2 zp = *(ulonglong2*)&zs[(warp * 8 + r) * 128 + k];  // (z0,z1),(z2,z3)
            ffma2(acc[r][0], zp.x, wa0.x);
            ffma2(acc[r][1], zp.x, wa0.y);
            ffma2(acc[r][2], zp.x, wa1.x);
            ffma2(acc[r][3], zp.x, wa1.y);
            ffma2(acc[r][0], zp.y, wb0.x);
            ffma2(acc[r][1], zp.y, wb0.y);
            ffma2(acc[r][2], zp.y, wb1.x);
            ffma2(acc[r][3], zp.y, wb1.y);
        }
    }

    // store + local BN1 stats
    float4 bb = ((const float4*)b)[lane];
    float4 s = make_float4(0.f, 0.f, 0.f, 0.f);
    float4 q = make_float4(0.f, 0.f, 0.f, 0.f);
    float4* y4 = (float4*)g_y;
    #pragma unroll
    for (int r = 0; r < 8; r++) {
        int row = row0 + warp * 8 + r;
        if (row < N_NODES) {
            float lo, hi;
            float4 v;
            unpk2(lo, hi, acc[r][0]); v.x = lo + hi + bb.x;
            unpk2(lo, hi, acc[r][1]); v.y = lo + hi + bb.y;
            unpk2(lo, hi, acc[r][2]); v.z = lo + hi + bb.z;
            unpk2(lo, hi, acc[r][3]); v.w = lo + hi + bb.w;
            y4[(size_t)row * 32 + lane] = v;
            s.x += v.x; s.y += v.y; s.z += v.z; s.w += v.w;
            q.x += v.x * v.x; q.y += v.y * v.y; q.z += v.z * v.z; q.w += v.w * v.w;
        }
    }
    rs[warp * 128 + c0 + 0] = s.x; rs[warp * 128 + c0 + 1] = s.y;
    rs[warp * 128 + c0 + 2] = s.z; rs[warp * 128 + c0 + 3] = s.w;
    rs[1024 + warp * 128 + c0 + 0] = q.x; rs[1024 + warp * 128 + c0 + 1] = q.y;
    rs[1024 + warp * 128 + c0 + 2] = q.z; rs[1024 + warp * 128 + c0 + 3] = q.w;
    __syncthreads();

    int col = tid & 127;
    int so = (tid >> 7) * 1024;
    float v = 0.f;
    #pragma unroll
    for (int w = 0; w < 8; w++) v += rs[so + w * 128 + col];
    atomicAdd(&g_stats[(tid >> 7) * 128 + col], v);
}

// consume g_stats -> scale/shift slot `which`, re-zero g_stats (replay-invariant)
__global__ void finalize_k(const float* __restrict__ gamma, const float* __restrict__ beta,
                           int which) {
    int c = threadIdx.x;
    float sum = g_stats[c];
    float sq = g_stats[128 + c];
    float mean = sum * (1.0f / N_NODES);
    float var = sq * (1.0f / N_NODES) - mean * mean;
    float scl = rsqrtf(var + 1e-5f) * gamma[c];
    g_scale[which][c] = scl;
    g_shift[which][c] = beta[c] - mean * scl;
    g_stats[c] = 0.f;
    g_stats[128 + c] = 0.f;
}

// read-only: apply BN1+ReLU on the fly, accumulate BN2 stats (no writeback)
__global__ void bn_relu_stats_k() {
    __shared__ float rs[2048];
    int tid = threadIdx.x, lane = tid & 31, warp = tid >> 5;
    float4 sc = ((const float4*)g_scale[0])[lane];
    float4 sh = ((const float4*)g_shift[0])[lane];
    float4 s = make_float4(0.f, 0.f, 0.f, 0.f);
    float4 q = make_float4(0.f, 0.f, 0.f, 0.f);
    const float4* y4 = (const float4*)g_y;
    int n4 = ND / 4;
    for (int i = blockIdx.x * 256 + tid; i < n4; i += gridDim.x * 256) {
        float4 v = y4[i];
        v.x = fmaxf(fmaf(v.x, sc.x, sh.x), 0.f);
        v.y = fmaxf(fmaf(v.y, sc.y, sh.y), 0.f);
        v.z = fmaxf(fmaf(v.z, sc.z, sh.z), 0.f);
        v.w = fmaxf(fmaf(v.w, sc.w, sh.w), 0.f);
        s.x += v.x; s.y += v.y; s.z += v.z; s.w += v.w;
        q.x += v.x * v.x; q.y += v.y * v.y; q.z += v.z * v.z; q.w += v.w * v.w;
    }
    int c0 = lane * 4;
    rs[warp * 128 + c0 + 0] = s.x; rs[warp * 128 + c0 + 1] = s.y;
    rs[warp * 128 + c0 + 2] = s.z; rs[warp * 128 + c0 + 3] = s.w;
    rs[1024 + warp * 128 + c0 + 0] = q.x; rs[1024 + warp * 128 + c0 + 1] = q.y;
    rs[1024 + warp * 128 + c0 + 2] = q.z; rs[1024 + warp * 128 + c0 + 3] = q.w;
    __syncthreads();
    int col = tid & 127;
    int so = (tid >> 7) * 1024;
    float v = 0.f;
    #pragma unroll
    for (int w = 0; w < 8; w++) v += rs[so + w * 128 + col];
    atomicAdd(&g_stats[(tid >> 7) * 128 + col], v);
}

// out = relu(bn2(relu(bn1(y))))  -> next layer's h (single pass from raw y)
__global__ void bn_relu_out_k(float* __restrict__ out) {
    int tid = threadIdx.x, lane = tid & 31;
    float4 sc1 = ((const float4*)g_scale[0])[lane];
    float4 sh1 = ((const float4*)g_shift[0])[lane];
    float4 sc2 = ((const float4*)g_scale[1])[lane];
    float4 sh2 = ((const float4*)g_shift[1])[lane];
    const float4* y4 = (const float4*)g_y;
    float4* o4 = (float4*)out;
    int n4 = ND / 4;
    for (int i = blockIdx.x * 256 + tid; i < n4; i += gridDim.x * 256) {
        float4 v = y4[i];
        v.x = fmaxf(fmaf(v.x, sc1.x, sh1.x), 0.f);
        v.y = fmaxf(fmaf(v.y, sc1.y, sh1.y), 0.f);
        v.z = fmaxf(fmaf(v.z, sc1.z, sh1.z), 0.f);
        v.w = fmaxf(fmaf(v.w, sc1.w, sh1.w), 0.f);
        v.x = fmaxf(fmaf(v.x, sc2.x, sh2.x), 0.f);
        v.y = fmaxf(fmaf(v.y, sc2.y, sh2.y), 0.f);
        v.z = fmaxf(fmaf(v.z, sc2.z, sh2.z), 0.f);
        v.w = fmaxf(fmaf(v.w, sc2.w, sh2.w), 0.f);
        o4[i] = v;
    }
}

extern "C" void kernel_launch(void* const* d_in, const int* in_sizes, int n_in,
                              void* d_out, int out_size) {
    const float* features = (const float*)d_in[0];
    const float* W   = (const float*)d_in[1];
    const float* b   = (const float*)d_in[2];
    const float* eps = (const float*)d_in[3];
    const float* g1  = (const float*)d_in[4];
    const float* be1 = (const float*)d_in[5];
    const float* g2  = (const float*)d_in[6];
    const float* be2 = (const float*)d_in[7];
    const int* src   = (const int*)d_in[8];
    const int* dst   = (const int*)d_in[9];
    int nE = in_sizes[8];
    float* out = (float*)d_out;

    static bool once = []() {
        cudaFuncSetAttribute(gather_gemm_stats_k, cudaFuncAttributeMaxDynamicSharedMemorySize,
                             GEMM_SMEM_BYTES);
        return true;
    }();
    (void)once;

    // slab 0 = input features
    cudaMemcpyAsync(out, features, (size_t)ND * sizeof(float), cudaMemcpyDeviceToDevice);

    // build CSR (dst -> list of src) once
    zero_deg_k<<<392, 256>>>();
    hist_k<<<6250, 256>>>(dst, nE);
    scan_k<<<1, 1024>>>(nE);
    fill_k<<<6250, 256>>>(src, dst, nE);

    for (int i = 0; i < 3; i++) {
        const float* h = out + (size_t)i * ND;
        float* hn = out + (size_t)(i + 1) * ND;
        gather_gemm_stats_k<<<(N_NODES + GROWS - 1) / GROWS, 256, GEMM_SMEM_BYTES>>>(
            h, W + (size_t)i * D * D, b + (size_t)i * D, eps, i);
        finalize_k<<<1, 128>>>(g1 + i * D, be1 + i * D, 0);
        bn_relu_stats_k<<<1184, 256>>>();
        finalize_k<<<1, 128>>>(g2 + i * D, be2 + i * D, 1);
        bn_relu_out_k<<<1184, 256>>>(hn);
    }
}